// round 12
// baseline (speedup 1.0000x reference)
#include <cuda_runtime.h>
#include <cuda_fp16.h>
#include <cstdint>

// SubLSTM: T=512, B=64, I=H=1024, L=2, gates (i,o,z), fixed forget fg=sigmoid(f)
//   gates = sigmoid(x W^T + h R^T + bi + bh)
//   c' = c*fg + z - i ;  h' = sigmoid(c') - o
// Output: [out (T*B*H)][h0_fin][h1_fin][c0_fin][c1_fin]

#define T_STEPS 512
#define BATCH   64
#define HSZ     1024
#define G3      3072
#define TBH     (T_STEPS * BATCH * HSZ)
#define BH      (BATCH * HSZ)
#define NB      64                   // recurrence grid: 64 CTAs x 16 cols
#define HSLOTH  (HSZ * BATCH)        // 65536 halves per h slot

// Device-global scratch (allocation-free rule)
__device__ float  g_gx[(size_t)T_STEPS * BATCH * G3];   // [t][3072][64]
__device__ float  g_h0[(size_t)T_STEPS * BATCH * HSZ];  // [t][b][h] layer-0 out
// h ping-pong (2 slots), fp16, A-FRAGMENT order for m16n8k16:
//   half idx = kb*1024 + (b>>4)*256 + lane*8 + (hi*4 + hb8*2 + lo)
__device__ __half g_htrh[2 * HSLOTH];
__device__ unsigned g_arrive;                 // legacy atomic barrier (init only)
__device__ unsigned g_gen;
__device__ volatile unsigned g_flags[NB * 32]; // per-CTA step flags, 128B stride

__device__ __forceinline__ float sigf(float x) { return 1.f / (1.f + __expf(-x)); }

// ===================== PTX helpers =====================
__device__ __forceinline__ uint32_t smem_u32(const void* p) {
    uint32_t a;
    asm("{ .reg .u64 t; cvta.to.shared.u64 t, %1; cvt.u32.u64 %0, t; }" : "=r"(a) : "l"(p));
    return a;
}
#define CP_ASYNC16(dst, src) \
    asm volatile("cp.async.ca.shared.global [%0], [%1], 16;" :: "r"(dst), "l"(src) : "memory")
#define CP_ASYNC_CG16(dst, src) \
    asm volatile("cp.async.cg.shared.global [%0], [%1], 16;" :: "r"(dst), "l"(src) : "memory")
#define CP_COMMIT() asm volatile("cp.async.commit_group;" ::: "memory")
#define CPWAIT(n)   asm volatile("cp.async.wait_group %0;" :: "n"(n) : "memory")

__device__ __forceinline__ uint32_t f2tf32(float x) {
    uint32_t u;
    asm("cvt.rna.tf32.f32 %0, %1;" : "=r"(u) : "f"(x));
    return u;
}
__device__ __forceinline__ void mma_tf32(float& d0, float& d1, float& d2, float& d3,
                                         uint32_t a0, uint32_t a1, uint32_t a2, uint32_t a3,
                                         uint32_t b0, uint32_t b1) {
    asm volatile("mma.sync.aligned.m16n8k8.row.col.f32.tf32.tf32.f32 "
                 "{%0,%1,%2,%3}, {%4,%5,%6,%7}, {%8,%9}, {%0,%1,%2,%3};"
                 : "+f"(d0), "+f"(d1), "+f"(d2), "+f"(d3)
                 : "r"(a0), "r"(a1), "r"(a2), "r"(a3), "r"(b0), "r"(b1));
}
__device__ __forceinline__ void mma_f16(float& d0, float& d1, float& d2, float& d3,
                                        uint32_t a0, uint32_t a1, uint32_t a2, uint32_t a3,
                                        uint32_t b0, uint32_t b1) {
    asm volatile("mma.sync.aligned.m16n8k16.row.col.f32.f16.f16.f32 "
                 "{%0,%1,%2,%3}, {%4,%5,%6,%7}, {%8,%9}, {%0,%1,%2,%3};"
                 : "+f"(d0), "+f"(d1), "+f"(d2), "+f"(d3)
                 : "r"(a0), "r"(a1), "r"(a2), "r"(a3), "r"(b0), "r"(b1));
}

// Legacy generation barrier (atomic). Used ONCE per launch to fence init.
__device__ __forceinline__ void grid_sync_atomic() {
    __threadfence();
    __syncthreads();
    if (threadIdx.x == 0) {
        unsigned gen = *(volatile unsigned*)&g_gen;
        unsigned t = atomicInc(&g_arrive, NB - 1);
        if (t == NB - 1) {
            __threadfence();
            *(volatile unsigned*)&g_gen = gen + 1;
        } else {
            while (*(volatile unsigned*)&g_gen == gen) { }
        }
        __threadfence();
    }
    __syncthreads();
}

// Per-step flag barrier over NB CTAs (distinct L2 lines per flag).
__device__ __forceinline__ void flag_barrier(unsigned val) {
    __threadfence();
    __syncthreads();
    if (threadIdx.x == 0) g_flags[blockIdx.x * 32] = val;
    if (threadIdx.x < NB) {
        while (g_flags[threadIdx.x * 32] < val) { }
    }
    __threadfence();
    __syncthreads();
}

// ---------------------------------------------------------------------------
// TF32 mma.sync GEMM (unchanged, passing)
// ---------------------------------------------------------------------------
#define SMPAD 36
__global__ __launch_bounds__(256, 2) void gemm_tf32_kernel(
    const float* __restrict__ A, const float* __restrict__ W,
    const float* __restrict__ bi, const float* __restrict__ bh,
    float* __restrict__ C)
{
    __shared__ float smA[128 * SMPAD];
    __shared__ float smB[128 * SMPAD];

    const int tid = threadIdx.x;
    const int wid = tid >> 5;
    const int lane = tid & 31;
    const int g   = lane >> 2;
    const int tig = lane & 3;
    const int wm  = wid & 3;
    const int wn  = wid >> 2;
    const int m0  = blockIdx.y * 128;
    const int n0  = blockIdx.x * 128;

    const uint32_t sa = smem_u32(smA);
    const uint32_t sb = smem_u32(smB);

    float acc[2][8][4];
#pragma unroll
    for (int mt = 0; mt < 2; mt++)
#pragma unroll
        for (int nt = 0; nt < 8; nt++)
#pragma unroll
            for (int r = 0; r < 4; r++) acc[mt][nt][r] = 0.f;

    const int lrow = tid >> 3;
    const int lq   = tid & 7;

#pragma unroll 1
    for (int kt = 0; kt < HSZ / 32; kt++) {
        const int k0 = kt * 32;
#pragma unroll
        for (int i = 0; i < 4; i++) {
            const int row = lrow + i * 32;
            CP_ASYNC16(sa + (uint32_t)(row * SMPAD + lq * 4) * 4,
                       A + (size_t)(m0 + row) * HSZ + k0 + lq * 4);
            CP_ASYNC16(sb + (uint32_t)(row * SMPAD + lq * 4) * 4,
                       W + (size_t)(n0 + row) * HSZ + k0 + lq * 4);
        }
        CP_COMMIT();
        CPWAIT(0);
        __syncthreads();

#pragma unroll
        for (int s = 0; s < 4; s++) {
            const int kc = s * 8 + tig;
            uint32_t af[2][4];
#pragma unroll
            for (int mt = 0; mt < 2; mt++) {
                const int r0 = (wm * 32 + mt * 16 + g) * SMPAD;
                af[mt][0] = f2tf32(smA[r0 + kc]);
                af[mt][1] = f2tf32(smA[r0 + 8 * SMPAD + kc]);
                af[mt][2] = f2tf32(smA[r0 + kc + 4]);
                af[mt][3] = f2tf32(smA[r0 + 8 * SMPAD + kc + 4]);
            }
#pragma unroll
            for (int nt = 0; nt < 8; nt++) {
                const int nr = (wn * 64 + nt * 8 + g) * SMPAD;
                uint32_t b0 = f2tf32(smB[nr + kc]);
                uint32_t b1 = f2tf32(smB[nr + kc + 4]);
#pragma unroll
                for (int mt = 0; mt < 2; mt++)
                    mma_tf32(acc[mt][nt][0], acc[mt][nt][1], acc[mt][nt][2], acc[mt][nt][3],
                             af[mt][0], af[mt][1], af[mt][2], af[mt][3], b0, b1);
            }
        }
        __syncthreads();
    }

    float* stage = smA;
    const int m_lane = tid & 63;
    const int n_off  = tid >> 6;
#pragma unroll 1
    for (int ci = 0; ci < 4; ci++) {
        if (wn == (ci >> 1)) {
            const int ntb = (ci & 1) * 4;
#pragma unroll
            for (int mt = 0; mt < 2; mt++) {
                const int r0 = wm * 32 + mt * 16 + g;
#pragma unroll
                for (int nn = 0; nn < 4; nn++) {
                    const int nt = ntb + nn;
                    const int nl = nn * 8 + 2 * tig;
                    stage[r0 * 33 + nl]           = acc[mt][nt][0];
                    stage[r0 * 33 + nl + 1]       = acc[mt][nt][1];
                    stage[(r0 + 8) * 33 + nl]     = acc[mt][nt][2];
                    stage[(r0 + 8) * 33 + nl + 1] = acc[mt][nt][3];
                }
            }
        }
        __syncthreads();
#pragma unroll
        for (int p = 0; p < 8; p++) {
            const int nlc = p * 4 + n_off;
            const int ng  = n0 + ci * 32 + nlc;
            const float bias = __ldg(bi + ng) + __ldg(bh + ng);
#pragma unroll
            for (int half = 0; half < 2; half++) {
                const int m  = m_lane + half * 64;
                const int mg = m0 + m;
                C[((size_t)(mg >> 6) * G3 + ng) * BATCH + (mg & 63)] =
                    stage[m * 33 + nlc] + bias;
            }
        }
        __syncthreads();
    }
}

// ---------------------------------------------------------------------------
// Persistent fp16 MMA recurrence: 64 CTAs x 256 threads (2 warp-groups),
// 16 H-cols per CTA (two col-groups A/B). Group g owns K-chunks 4g..4g+3
// with its own cp.async pipeline (3 x 16KB bufs, named barrier). R resident
// in B-fragment order (96KB). Accumulators reduced via smem scratch.
// Smem: 96KB R + 96KB A bufs + 12KB scratch = 204KB.
// ---------------------------------------------------------------------------
__global__ __launch_bounds__(256) void recurrent_kernel(
    const float* __restrict__ gx,   // [T][3072][64]
    const float* __restrict__ R,    // [3072][1024]
    const float* __restrict__ f,    // [1024]
    float* __restrict__ hb,         // [T][B][H]
    float* __restrict__ hfin,       // [B][H]
    float* __restrict__ cfin)       // [B][H]
{
    extern __shared__ __align__(16) char s_dyn[];
    __half* Rsh = (__half*)s_dyn;               // 98304 B (B-frag order, 6 nt)
    char*   Asm = s_dyn + 98304;                // 6 bufs x 16384 B
    float*  red = (float*)(s_dyn + 98304 + 98304);  // 12288 B scratch

    const int tid  = threadIdx.x;
    const int wid  = tid >> 5;
    const int grp  = wid >> 2;          // warp-group 0/1
    const int wm   = wid & 3;
    const int gtid = tid & 127;
    const int lane = tid & 31;
    const int g    = lane >> 2;
    const int tig  = lane & 3;
    const int bid  = blockIdx.x;
    const int colbase = bid * 16;
    const int gb   = grp * 4;           // first global chunk of this group

    if (tid == 0) g_flags[bid * 32] = 0;

    // ---- Load R slice (48 rows x 1024) -> B-fragment-order fp16 smem ----
    for (int v = tid; v < 12288; v += 256) {
        const int n  = v >> 8;              // 0..47: gate*16 + colloc
        const int k  = (v & 255) * 4;
        const int gate = n >> 4, colloc = n & 15;
        const int nt = n >> 3, nloc = n & 7;
        const int row = gate * HSZ + colbase + colloc;
        float4 w = *(const float4*)(R + (size_t)row * HSZ + k);
        const int kb = k >> 4, kin = k & 15;
        const int t0 = (kin & 7) >> 1;
        const int hi = kin >> 3;
        __half* base = Rsh + (((kb * 6 + nt) * 32 + nloc * 4) * 4 + hi * 2);
        *(__half2*)(base + (t0    ) * 4) = __floats2half2_rn(w.x, w.y);
        *(__half2*)(base + (t0 + 1) * 4) = __floats2half2_rn(w.z, w.w);
    }

    grid_sync_atomic();   // flag resets + R smem visible/done

    const int r0 = wm * 16 + g;
    const int r1 = r0 + 8;
    const int cA = colbase + 2 * tig;        // col-group A (nt even)
    const int cB = colbase + 8 + 2 * tig;    // col-group B (nt odd)
    const float fgA0 = sigf(__ldg(f + cA)),     fgA1 = sigf(__ldg(f + cA + 1));
    const float fgB0 = sigf(__ldg(f + cB)),     fgB1 = sigf(__ldg(f + cB + 1));
    float csA00 = 0.f, csA01 = 0.f, csA10 = 0.f, csA11 = 0.f;
    float csB00 = 0.f, csB01 = 0.f, csB10 = 0.f, csB11 = 0.f;

    const uint32_t hsA  = smem_u32(Asm);
    const uint32_t grpb = (uint32_t)grp * 3 * 16384;
    const uint32_t a_lm = hsA + grpb + (uint32_t)(wm * 512 + lane * 16);
    // producer h write: 8 contiguous halves (col-groups A: +0..3, B: +4..7)
    const int wp = bid * 1024 + wm * 256 + lane * 8;

#define BARG() asm volatile("bar.sync %0, 128;" :: "r"(grp + 1) : "memory")
#define ISSUE(cglob, buf) do {                                                   \
        const char* s_ = (const char*)hsrc + (size_t)(cglob) * 16384 + gtid * 16; \
        uint32_t d_ = hsA + grpb + (uint32_t)(buf) * 16384 + (uint32_t)(gtid * 16); \
        _Pragma("unroll")                                                        \
        for (int j_ = 0; j_ < 8; j_++)                                           \
            CP_ASYNC_CG16(d_ + j_ * 2048, s_ + j_ * 2048);                       \
        CP_COMMIT();                                                             \
    } while (0)

#pragma unroll 1
    for (int t = 0; t < T_STEPS; t++) {
        float a[6][4];
#pragma unroll
        for (int nt = 0; nt < 6; nt++)
#pragma unroll
            for (int r = 0; r < 4; r++) a[nt][r] = 0.f;

        if (t > 0) {
            const __half* hsrc = g_htrh + (size_t)((t - 1) & 1) * HSLOTH;
            ISSUE(gb + 0, 0);
            ISSUE(gb + 1, 1);
#pragma unroll 1
            for (int l = 0; l < 4; l++) {
                if (l == 3) CPWAIT(0); else CPWAIT(1);
                BARG();
                if (l < 2) ISSUE(gb + l + 2, (l + 2) % 3);
                const uint32_t a_ch = a_lm + (uint32_t)(l % 3) * 16384;
#pragma unroll
                for (int blk = 0; blk < 8; blk++) {
                    uint4 Af;
                    asm volatile("ld.shared.v4.b32 {%0,%1,%2,%3}, [%4];"
                                 : "=r"(Af.x), "=r"(Af.y), "=r"(Af.z), "=r"(Af.w)
                                 : "r"(a_ch + (uint32_t)(blk * 2048)));
                    const int kbg = (gb + l) * 8 + blk;
                    const uint2* bf = (const uint2*)((const char*)Rsh
                                      + (size_t)(kbg * 6) * 256 + lane * 8);
#pragma unroll
                    for (int nt = 0; nt < 6; nt++) {
                        const uint2 Bf = bf[nt * 32];
                        mma_f16(a[nt][0], a[nt][1], a[nt][2], a[nt][3],
                                Af.x, Af.y, Af.z, Af.w, Bf.x, Bf.y);
                    }
                }
            }
        }

        // gx preactivations (grp 0 only) -- issued here so LDG latency
        // overlaps the cross-group reduction below.
        float xg[6][4];
        if (grp == 0) {
            const float* gxt = gx + (size_t)t * G3 * BATCH;
#pragma unroll
            for (int gg = 0; gg < 3; gg++) {
                const float* p0 = gxt + (size_t)(gg * HSZ + cA) * BATCH;
                const float* p1 = gxt + (size_t)(gg * HSZ + cB) * BATCH;
                xg[gg * 2    ][0] = __ldcg(p0 + r0);
                xg[gg * 2    ][1] = __ldcg(p0 + BATCH + r0);
                xg[gg * 2    ][2] = __ldcg(p0 + r1);
                xg[gg * 2    ][3] = __ldcg(p0 + BATCH + r1);
                xg[gg * 2 + 1][0] = __ldcg(p1 + r0);
                xg[gg * 2 + 1][1] = __ldcg(p1 + BATCH + r0);
                xg[gg * 2 + 1][2] = __ldcg(p1 + r1);
                xg[gg * 2 + 1][3] = __ldcg(p1 + BATCH + r1);
            }
        }

        if (t > 0) {
            // ---- reduce group-1 partials into group-0 accumulators ----
            __syncthreads();
            if (grp == 1) {
                float* d = red + gtid * 24;
#pragma unroll
                for (int nt = 0; nt < 6; nt++)
#pragma unroll
                    for (int r = 0; r < 4; r++) d[nt * 4 + r] = a[nt][r];
            }
            __syncthreads();
            if (grp == 0) {
                const float* s = red + gtid * 24;
#pragma unroll
                for (int nt = 0; nt < 6; nt++)
#pragma unroll
                    for (int r = 0; r < 4; r++) a[nt][r] += s[nt * 4 + r];
            }
        }

        // ---- epilogue (grp 0): gates, cell, hidden for both col-groups ----
        if (grp == 0) {
            // gate index mapping: nt = gate*2 + colgrp  (i:0/1, o:2/3, z:4/5)
            const float iA0 = sigf(a[0][0] + xg[0][0]), iA1 = sigf(a[0][1] + xg[0][1]);
            const float iA2 = sigf(a[0][2] + xg[0][2]), iA3 = sigf(a[0][3] + xg[0][3]);
            const float iB0 = sigf(a[1][0] + xg[1][0]), iB1 = sigf(a[1][1] + xg[1][1]);
            const float iB2 = sigf(a[1][2] + xg[1][2]), iB3 = sigf(a[1][3] + xg[1][3]);
            const float oA0 = sigf(a[2][0] + xg[2][0]), oA1 = sigf(a[2][1] + xg[2][1]);
            const float oA2 = sigf(a[2][2] + xg[2][2]), oA3 = sigf(a[2][3] + xg[2][3]);
            const float oB0 = sigf(a[3][0] + xg[3][0]), oB1 = sigf(a[3][1] + xg[3][1]);
            const float oB2 = sigf(a[3][2] + xg[3][2]), oB3 = sigf(a[3][3] + xg[3][3]);
            const float zA0 = sigf(a[4][0] + xg[4][0]), zA1 = sigf(a[4][1] + xg[4][1]);
            const float zA2 = sigf(a[4][2] + xg[4][2]), zA3 = sigf(a[4][3] + xg[4][3]);
            const float zB0 = sigf(a[5][0] + xg[5][0]), zB1 = sigf(a[5][1] + xg[5][1]);
            const float zB2 = sigf(a[5][2] + xg[5][2]), zB3 = sigf(a[5][3] + xg[5][3]);

            csA00 = csA00 * fgA0 + zA0 - iA0;
            csA01 = csA01 * fgA1 + zA1 - iA1;
            csA10 = csA10 * fgA0 + zA2 - iA2;
            csA11 = csA11 * fgA1 + zA3 - iA3;
            csB00 = csB00 * fgB0 + zB0 - iB0;
            csB01 = csB01 * fgB1 + zB1 - iB1;
            csB10 = csB10 * fgB0 + zB2 - iB2;
            csB11 = csB11 * fgB1 + zB3 - iB3;

            const float hA00 = sigf(csA00) - oA0;
            const float hA01 = sigf(csA01) - oA1;
            const float hA10 = sigf(csA10) - oA2;
            const float hA11 = sigf(csA11) - oA3;
            const float hB00 = sigf(csB00) - oB0;
            const float hB01 = sigf(csB01) - oB1;
            const float hB10 = sigf(csB10) - oB2;
            const float hB11 = sigf(csB11) - oB3;

            // h -> fp16 A-fragment ping-pong: 8 contiguous halves = STG.128
            {
                __half2 pA0 = __floats2half2_rn(hA00, hA01);
                __half2 pA1 = __floats2half2_rn(hA10, hA11);
                __half2 pB0 = __floats2half2_rn(hB00, hB01);
                __half2 pB1 = __floats2half2_rn(hB10, hB11);
                uint4 pk;
                pk.x = *(unsigned*)&pA0;
                pk.y = *(unsigned*)&pA1;
                pk.z = *(unsigned*)&pB0;
                pk.w = *(unsigned*)&pB1;
                __half* slot = g_htrh + (size_t)(t & 1) * HSLOTH + wp;
                __stcg((uint4*)slot, pk);
            }

            // h -> sequence output [t][b][h] (full precision)
            float* hbt = hb + (size_t)t * BH;
            __stcg((float2*)(hbt + (size_t)r0 * HSZ + cA), make_float2(hA00, hA01));
            __stcg((float2*)(hbt + (size_t)r1 * HSZ + cA), make_float2(hA10, hA11));
            __stcg((float2*)(hbt + (size_t)r0 * HSZ + cB), make_float2(hB00, hB01));
            __stcg((float2*)(hbt + (size_t)r1 * HSZ + cB), make_float2(hB10, hB11));

            if (t == T_STEPS - 1) {
                *(float2*)(hfin + (size_t)r0 * HSZ + cA) = make_float2(hA00, hA01);
                *(float2*)(hfin + (size_t)r1 * HSZ + cA) = make_float2(hA10, hA11);
                *(float2*)(hfin + (size_t)r0 * HSZ + cB) = make_float2(hB00, hB01);
                *(float2*)(hfin + (size_t)r1 * HSZ + cB) = make_float2(hB10, hB11);
                *(float2*)(cfin + (size_t)r0 * HSZ + cA) = make_float2(csA00, csA01);
                *(float2*)(cfin + (size_t)r1 * HSZ + cA) = make_float2(csA10, csA11);
                *(float2*)(cfin + (size_t)r0 * HSZ + cB) = make_float2(csB00, csB01);
                *(float2*)(cfin + (size_t)r1 * HSZ + cB) = make_float2(csB10, csB11);
            }
        }

        if (t < T_STEPS - 1) flag_barrier((unsigned)(t + 1));
    }
#undef ISSUE
#undef BARG
}

// ---------------------------------------------------------------------------
extern "C" void kernel_launch(void* const* d_in, const int* in_sizes, int n_in,
                              void* d_out, int out_size)
{
    const float* x   = (const float*)d_in[0];
    const float* W0  = (const float*)d_in[1];
    const float* R0  = (const float*)d_in[2];
    const float* bi0 = (const float*)d_in[3];
    const float* bh0 = (const float*)d_in[4];
    const float* f0  = (const float*)d_in[5];
    const float* W1  = (const float*)d_in[6];
    const float* R1  = (const float*)d_in[7];
    const float* bi1 = (const float*)d_in[8];
    const float* bh1 = (const float*)d_in[9];
    const float* f1  = (const float*)d_in[10];
    float* out = (float*)d_out;

    float *gx, *h0;
    cudaGetSymbolAddress((void**)&gx, g_gx);
    cudaGetSymbolAddress((void**)&h0, g_h0);

    const int RSMEM = 98304 + 98304 + 12288;   // 208896 B
    cudaFuncSetAttribute(recurrent_kernel,
                         cudaFuncAttributeMaxDynamicSharedMemorySize, RSMEM);

    dim3 ggrid(G3 / 128, (T_STEPS * BATCH) / 128);   // (24, 256)

    // Layer 0
    gemm_tf32_kernel<<<ggrid, 256>>>(x, W0, bi0, bh0, gx);
    recurrent_kernel<<<NB, 256, RSMEM>>>(gx, R0, f0, h0,
                                         out + TBH,              // h0 final
                                         out + TBH + 2 * BH);    // c0 final
    // Layer 1
    gemm_tf32_kernel<<<ggrid, 256>>>(h0, W1, bi1, bh1, gx);
    recurrent_kernel<<<NB, 256, RSMEM>>>(gx, R1, f1, out,
                                         out + TBH + BH,         // h1 final
                                         out + TBH + 3 * BH);    // c1 final
}

// round 13
// speedup vs baseline: 1.3052x; 1.3052x over previous
#include <cuda_runtime.h>
#include <cuda_fp16.h>
#include <cstdint>

// SubLSTM: T=512, B=64, I=H=1024, L=2, gates (i,o,z), fixed forget fg=sigmoid(f)
//   gates = sigmoid(x W^T + h R^T + bi + bh)
//   c' = c*fg + z - i ;  h' = sigmoid(c') - o
// Output: [out (T*B*H)][h0_fin][h1_fin][c0_fin][c1_fin]

#define T_STEPS 512
#define BATCH   64
#define HSZ     1024
#define G3      3072
#define TBH     (T_STEPS * BATCH * HSZ)
#define BH      (BATCH * HSZ)
#define NB      128
#define HSLOTH  (HSZ * BATCH)        // 65536 halves per h slot

// Device-global scratch (allocation-free rule)
__device__ float  g_gx[(size_t)T_STEPS * BATCH * G3];   // [t][3072][64]
__device__ float  g_h0[(size_t)T_STEPS * BATCH * HSZ];  // [t][b][h] layer-0 out
// h ping-pong (2 slots), fp16, A-FRAGMENT order for m16n8k16:
//   half idx = kb*1024 + (b>>4)*256 + lane*8 + (hi*4 + hb8*2 + lo)
__device__ __half g_htrh[2 * HSLOTH];
__device__ unsigned g_arrive;                 // legacy atomic barrier (init only)
__device__ unsigned g_gen;
__device__ unsigned g_flags[NB * 32];         // per-CTA step flags, 128B stride

__device__ __forceinline__ float sigf(float x) { return 1.f / (1.f + __expf(-x)); }

// ===================== PTX helpers =====================
__device__ __forceinline__ uint32_t smem_u32(const void* p) {
    uint32_t a;
    asm("{ .reg .u64 t; cvta.to.shared.u64 t, %1; cvt.u32.u64 %0, t; }" : "=r"(a) : "l"(p));
    return a;
}
#define CP_ASYNC16(dst, src) \
    asm volatile("cp.async.ca.shared.global [%0], [%1], 16;" :: "r"(dst), "l"(src) : "memory")
#define CP_ASYNC_CG16(dst, src) \
    asm volatile("cp.async.cg.shared.global [%0], [%1], 16;" :: "r"(dst), "l"(src) : "memory")
#define CP_COMMIT() asm volatile("cp.async.commit_group;" ::: "memory")
#define CPWAIT(n)   asm volatile("cp.async.wait_group %0;" :: "n"(n) : "memory")

__device__ __forceinline__ unsigned ld_acq(const unsigned* p) {
    unsigned v;
    asm volatile("ld.acquire.gpu.u32 %0, [%1];" : "=r"(v) : "l"(p) : "memory");
    return v;
}
__device__ __forceinline__ void st_rel(unsigned* p, unsigned v) {
    asm volatile("st.release.gpu.u32 [%0], %1;" :: "l"(p), "r"(v) : "memory");
}

__device__ __forceinline__ uint32_t f2tf32(float x) {
    uint32_t u;
    asm("cvt.rna.tf32.f32 %0, %1;" : "=r"(u) : "f"(x));
    return u;
}
__device__ __forceinline__ void mma_tf32(float& d0, float& d1, float& d2, float& d3,
                                         uint32_t a0, uint32_t a1, uint32_t a2, uint32_t a3,
                                         uint32_t b0, uint32_t b1) {
    asm volatile("mma.sync.aligned.m16n8k8.row.col.f32.tf32.tf32.f32 "
                 "{%0,%1,%2,%3}, {%4,%5,%6,%7}, {%8,%9}, {%0,%1,%2,%3};"
                 : "+f"(d0), "+f"(d1), "+f"(d2), "+f"(d3)
                 : "r"(a0), "r"(a1), "r"(a2), "r"(a3), "r"(b0), "r"(b1));
}
__device__ __forceinline__ void mma_f16(float& d0, float& d1, float& d2, float& d3,
                                        uint32_t a0, uint32_t a1, uint32_t a2, uint32_t a3,
                                        uint32_t b0, uint32_t b1) {
    asm volatile("mma.sync.aligned.m16n8k16.row.col.f32.f16.f16.f32 "
                 "{%0,%1,%2,%3}, {%4,%5,%6,%7}, {%8,%9}, {%0,%1,%2,%3};"
                 : "+f"(d0), "+f"(d1), "+f"(d2), "+f"(d3)
                 : "r"(a0), "r"(a1), "r"(a2), "r"(a3), "r"(b0), "r"(b1));
}

// Legacy generation barrier (atomic). Used ONCE per launch to fence init.
__device__ __forceinline__ void grid_sync_atomic() {
    __threadfence();
    __syncthreads();
    if (threadIdx.x == 0) {
        unsigned gen = *(volatile unsigned*)&g_gen;
        unsigned t = atomicInc(&g_arrive, NB - 1);
        if (t == NB - 1) {
            __threadfence();
            *(volatile unsigned*)&g_gen = gen + 1;
        } else {
            while (*(volatile unsigned*)&g_gen == gen) { }
        }
        __threadfence();
    }
    __syncthreads();
}

// Per-step flag barrier, fence-free: release store of own flag + acquire polls
// of all peers. Memory-model chain: stores -> syncthreads -> tid0 release ->
// peer acquire -> syncthreads -> reads. Requires blockDim.x >= NB.
__device__ __forceinline__ void flag_barrier(unsigned val) {
    __syncthreads();
    if (threadIdx.x == 0) st_rel(&g_flags[blockIdx.x * 32], val);
    if (threadIdx.x < NB) {
        while (ld_acq(&g_flags[threadIdx.x * 32]) < val) { }
    }
    __syncthreads();
}

// ---------------------------------------------------------------------------
// TF32 mma.sync GEMM (unchanged, passing)
// ---------------------------------------------------------------------------
#define SMPAD 36
__global__ __launch_bounds__(256, 2) void gemm_tf32_kernel(
    const float* __restrict__ A, const float* __restrict__ W,
    const float* __restrict__ bi, const float* __restrict__ bh,
    float* __restrict__ C)
{
    __shared__ float smA[128 * SMPAD];
    __shared__ float smB[128 * SMPAD];

    const int tid = threadIdx.x;
    const int wid = tid >> 5;
    const int lane = tid & 31;
    const int g   = lane >> 2;
    const int tig = lane & 3;
    const int wm  = wid & 3;
    const int wn  = wid >> 2;
    const int m0  = blockIdx.y * 128;
    const int n0  = blockIdx.x * 128;

    const uint32_t sa = smem_u32(smA);
    const uint32_t sb = smem_u32(smB);

    float acc[2][8][4];
#pragma unroll
    for (int mt = 0; mt < 2; mt++)
#pragma unroll
        for (int nt = 0; nt < 8; nt++)
#pragma unroll
            for (int r = 0; r < 4; r++) acc[mt][nt][r] = 0.f;

    const int lrow = tid >> 3;
    const int lq   = tid & 7;

#pragma unroll 1
    for (int kt = 0; kt < HSZ / 32; kt++) {
        const int k0 = kt * 32;
#pragma unroll
        for (int i = 0; i < 4; i++) {
            const int row = lrow + i * 32;
            CP_ASYNC16(sa + (uint32_t)(row * SMPAD + lq * 4) * 4,
                       A + (size_t)(m0 + row) * HSZ + k0 + lq * 4);
            CP_ASYNC16(sb + (uint32_t)(row * SMPAD + lq * 4) * 4,
                       W + (size_t)(n0 + row) * HSZ + k0 + lq * 4);
        }
        CP_COMMIT();
        CPWAIT(0);
        __syncthreads();

#pragma unroll
        for (int s = 0; s < 4; s++) {
            const int kc = s * 8 + tig;
            uint32_t af[2][4];
#pragma unroll
            for (int mt = 0; mt < 2; mt++) {
                const int r0 = (wm * 32 + mt * 16 + g) * SMPAD;
                af[mt][0] = f2tf32(smA[r0 + kc]);
                af[mt][1] = f2tf32(smA[r0 + 8 * SMPAD + kc]);
                af[mt][2] = f2tf32(smA[r0 + kc + 4]);
                af[mt][3] = f2tf32(smA[r0 + 8 * SMPAD + kc + 4]);
            }
#pragma unroll
            for (int nt = 0; nt < 8; nt++) {
                const int nr = (wn * 64 + nt * 8 + g) * SMPAD;
                uint32_t b0 = f2tf32(smB[nr + kc]);
                uint32_t b1 = f2tf32(smB[nr + kc + 4]);
#pragma unroll
                for (int mt = 0; mt < 2; mt++)
                    mma_tf32(acc[mt][nt][0], acc[mt][nt][1], acc[mt][nt][2], acc[mt][nt][3],
                             af[mt][0], af[mt][1], af[mt][2], af[mt][3], b0, b1);
            }
        }
        __syncthreads();
    }

    float* stage = smA;
    const int m_lane = tid & 63;
    const int n_off  = tid >> 6;
#pragma unroll 1
    for (int ci = 0; ci < 4; ci++) {
        if (wn == (ci >> 1)) {
            const int ntb = (ci & 1) * 4;
#pragma unroll
            for (int mt = 0; mt < 2; mt++) {
                const int r0 = wm * 32 + mt * 16 + g;
#pragma unroll
                for (int nn = 0; nn < 4; nn++) {
                    const int nt = ntb + nn;
                    const int nl = nn * 8 + 2 * tig;
                    stage[r0 * 33 + nl]           = acc[mt][nt][0];
                    stage[r0 * 33 + nl + 1]       = acc[mt][nt][1];
                    stage[(r0 + 8) * 33 + nl]     = acc[mt][nt][2];
                    stage[(r0 + 8) * 33 + nl + 1] = acc[mt][nt][3];
                }
            }
        }
        __syncthreads();
#pragma unroll
        for (int p = 0; p < 8; p++) {
            const int nlc = p * 4 + n_off;
            const int ng  = n0 + ci * 32 + nlc;
            const float bias = __ldg(bi + ng) + __ldg(bh + ng);
#pragma unroll
            for (int half = 0; half < 2; half++) {
                const int m  = m_lane + half * 64;
                const int mg = m0 + m;
                C[((size_t)(mg >> 6) * G3 + ng) * BATCH + (mg & 63)] =
                    stage[m * 33 + nlc] + bias;
            }
        }
        __syncthreads();
    }
}

// ---------------------------------------------------------------------------
// Persistent fp16 MMA recurrence: 128 CTAs x 512 threads = 4 warp-groups.
// Group g owns K-chunks 2g, 2g+1 with its own 2-buf cp.async pipeline and
// named barrier (grp+1). Partials reduced via smem scratch into group 0,
// which runs the epilogue (round-9/11 verified fragment layouts unchanged).
// Fence-free release/acquire flag barrier between steps.
// Smem: R 48KB + 8 x 16KB A bufs + 18KB scratch = 198.5KB.
// ---------------------------------------------------------------------------
__global__ __launch_bounds__(512) void recurrent_kernel(
    const float* __restrict__ gx,   // [T][3072][64]
    const float* __restrict__ R,    // [3072][1024]
    const float* __restrict__ f,    // [1024]
    float* __restrict__ hb,         // [T][B][H]
    float* __restrict__ hfin,       // [B][H]
    float* __restrict__ cfin)       // [B][H]
{
    extern __shared__ __align__(16) char s_dyn[];
    __half* Rsh = (__half*)s_dyn;               // 49152 B (B-frag order)
    char*   Asm = s_dyn + 49152;                // 8 bufs x 16384 B
    float*  red = (float*)(s_dyn + 49152 + 131072);  // 18432 B scratch

    const int tid  = threadIdx.x;
    const int wid  = tid >> 5;
    const int grp  = wid >> 2;          // warp-group 0..3
    const int wm   = wid & 3;
    const int gtid = tid & 127;
    const int lane = tid & 31;
    const int g    = lane >> 2;
    const int tig  = lane & 3;
    const int bid  = blockIdx.x;
    const int colbase = bid * 8;
    const int gb   = grp * 2;           // first global chunk of this group

    if (tid == 0) g_flags[bid * 32] = 0;

    // ---- Load R slice -> B-fragment-order fp16 smem, once ----
    for (int v = tid; v < 6144; v += 512) {
        const int n  = v >> 8;
        const int k  = (v & 255) * 4;
        const int nt = n >> 3, nloc = n & 7;
        const int row = nt * HSZ + colbase + nloc;
        float4 w = *(const float4*)(R + (size_t)row * HSZ + k);
        const int kb = k >> 4, kin = k & 15;
        const int t0 = (kin & 7) >> 1;
        const int hi = kin >> 3;
        __half* base = Rsh + (((kb * 3 + nt) * 32 + nloc * 4) * 4 + hi * 2);
        *(__half2*)(base + (t0    ) * 4) = __floats2half2_rn(w.x, w.y);
        *(__half2*)(base + (t0 + 1) * 4) = __floats2half2_rn(w.z, w.w);
    }

    grid_sync_atomic();   // flag resets + R smem visible/done

    const int r0 = wm * 16 + g;
    const int r1 = r0 + 8;
    const int c0g = colbase + 2 * tig;
    const int c1g = c0g + 1;
    const float fg0 = sigf(__ldg(f + c0g));
    const float fg1 = sigf(__ldg(f + c1g));
    float cs00 = 0.f, cs01 = 0.f, cs10 = 0.f, cs11 = 0.f;

    const uint32_t hsA  = smem_u32(Asm);
    const uint32_t grpb = (uint32_t)grp * 2 * 16384;
    const uint32_t a_lm = hsA + grpb + (uint32_t)(wm * 512 + lane * 16);
    const int wp = (colbase >> 4) * 1024 + wm * 256 + lane * 8
                 + ((colbase >> 3) & 1) * 4;

#define BARG() asm volatile("bar.sync %0, 128;" :: "r"(grp + 1) : "memory")
#define ISSUE(cglob, buf) do {                                                   \
        const char* s_ = (const char*)hsrc + (size_t)(cglob) * 16384 + gtid * 16; \
        uint32_t d_ = hsA + grpb + (uint32_t)(buf) * 16384 + (uint32_t)(gtid * 16); \
        _Pragma("unroll")                                                        \
        for (int j_ = 0; j_ < 8; j_++)                                           \
            CP_ASYNC_CG16(d_ + j_ * 2048, s_ + j_ * 2048);                       \
        CP_COMMIT();                                                             \
    } while (0)

#pragma unroll 1
    for (int t = 0; t < T_STEPS; t++) {
        // gx preactivations (group 0 only; early issue)
        float xi00 = 0.f, xi01 = 0.f, xi10 = 0.f, xi11 = 0.f;
        float xo00 = 0.f, xo01 = 0.f, xo10 = 0.f, xo11 = 0.f;
        float xz00 = 0.f, xz01 = 0.f, xz10 = 0.f, xz11 = 0.f;
        if (grp == 0) {
            const float* gxt = gx + (size_t)t * G3 * BATCH;
            xi00 = __ldcg(gxt + (size_t)c0g * BATCH + r0);
            xi01 = __ldcg(gxt + (size_t)c1g * BATCH + r0);
            xi10 = __ldcg(gxt + (size_t)c0g * BATCH + r1);
            xi11 = __ldcg(gxt + (size_t)c1g * BATCH + r1);
            xo00 = __ldcg(gxt + (size_t)(HSZ + c0g) * BATCH + r0);
            xo01 = __ldcg(gxt + (size_t)(HSZ + c1g) * BATCH + r0);
            xo10 = __ldcg(gxt + (size_t)(HSZ + c0g) * BATCH + r1);
            xo11 = __ldcg(gxt + (size_t)(HSZ + c1g) * BATCH + r1);
            xz00 = __ldcg(gxt + (size_t)(2 * HSZ + c0g) * BATCH + r0);
            xz01 = __ldcg(gxt + (size_t)(2 * HSZ + c1g) * BATCH + r0);
            xz10 = __ldcg(gxt + (size_t)(2 * HSZ + c0g) * BATCH + r1);
            xz11 = __ldcg(gxt + (size_t)(2 * HSZ + c1g) * BATCH + r1);
        }

        float a[3][4] = {{0.f,0.f,0.f,0.f},{0.f,0.f,0.f,0.f},{0.f,0.f,0.f,0.f}};

        if (t > 0) {
            const __half* hsrc = g_htrh + (size_t)((t - 1) & 1) * HSLOTH;
            ISSUE(gb + 0, 0);
            ISSUE(gb + 1, 1);
#pragma unroll
            for (int l = 0; l < 2; l++) {
                if (l == 0) CPWAIT(1); else CPWAIT(0);
                BARG();                  // chunk l landed group-wide
                const uint32_t a_ch = a_lm + (uint32_t)l * 16384;
#pragma unroll
                for (int blk = 0; blk < 8; blk++) {
                    uint4 Af;
                    asm volatile("ld.shared.v4.b32 {%0,%1,%2,%3}, [%4];"
                                 : "=r"(Af.x), "=r"(Af.y), "=r"(Af.z), "=r"(Af.w)
                                 : "r"(a_ch + (uint32_t)(blk * 2048)));
                    const int kbg = (gb + l) * 8 + blk;
                    const uint2* bf = (const uint2*)((const char*)Rsh
                                      + (size_t)(kbg * 3) * 256 + lane * 8);
#pragma unroll
                    for (int nt = 0; nt < 3; nt++) {
                        const uint2 Bf = bf[nt * 32];
                        mma_f16(a[nt][0], a[nt][1], a[nt][2], a[nt][3],
                                Af.x, Af.y, Af.z, Af.w, Bf.x, Bf.y);
                    }
                }
            }
            // ---- reduce groups 1-3 partials into group 0 ----
            __syncthreads();
            if (grp > 0) {
                float* d = red + (size_t)(grp - 1) * 1536 + gtid * 12;
#pragma unroll
                for (int nt = 0; nt < 3; nt++)
#pragma unroll
                    for (int r = 0; r < 4; r++) d[nt * 4 + r] = a[nt][r];
            }
            __syncthreads();
            if (grp == 0) {
#pragma unroll
                for (int s = 0; s < 3; s++) {
                    const float* sp = red + (size_t)s * 1536 + gtid * 12;
#pragma unroll
                    for (int nt = 0; nt < 3; nt++)
#pragma unroll
                        for (int r = 0; r < 4; r++) a[nt][r] += sp[nt * 4 + r];
                }
            }
        }

        // ---- epilogue (group 0 only): gates, cell, hidden ----
        if (grp == 0) {
            const float i00 = sigf(a[0][0] + xi00), i01 = sigf(a[0][1] + xi01);
            const float i10 = sigf(a[0][2] + xi10), i11 = sigf(a[0][3] + xi11);
            const float o00 = sigf(a[1][0] + xo00), o01 = sigf(a[1][1] + xo01);
            const float o10 = sigf(a[1][2] + xo10), o11 = sigf(a[1][3] + xo11);
            const float z00 = sigf(a[2][0] + xz00), z01 = sigf(a[2][1] + xz01);
            const float z10 = sigf(a[2][2] + xz10), z11 = sigf(a[2][3] + xz11);

            cs00 = cs00 * fg0 + z00 - i00;
            cs01 = cs01 * fg1 + z01 - i01;
            cs10 = cs10 * fg0 + z10 - i10;
            cs11 = cs11 * fg1 + z11 - i11;
            const float h00 = sigf(cs00) - o00;
            const float h01 = sigf(cs01) - o01;
            const float h10 = sigf(cs10) - o10;
            const float h11 = sigf(cs11) - o11;

            // h -> fp16 A-fragment ping-pong: 4 contiguous halves, one 8B store
            {
                __half2 p0 = __floats2half2_rn(h00, h01);
                __half2 p1 = __floats2half2_rn(h10, h11);
                uint2 pk;
                pk.x = *(unsigned*)&p0;
                pk.y = *(unsigned*)&p1;
                __half* slot = g_htrh + (size_t)(t & 1) * HSLOTH + wp;
                __stcg((uint2*)slot, pk);
            }

            // h -> sequence output [t][b][h] (full precision)
            float* hbt = hb + (size_t)t * BH;
            __stcg((float2*)(hbt + (size_t)r0 * HSZ + c0g), make_float2(h00, h01));
            __stcg((float2*)(hbt + (size_t)r1 * HSZ + c0g), make_float2(h10, h11));

            if (t == T_STEPS - 1) {
                *(float2*)(hfin + (size_t)r0 * HSZ + c0g) = make_float2(h00, h01);
                *(float2*)(hfin + (size_t)r1 * HSZ + c0g) = make_float2(h10, h11);
                *(float2*)(cfin + (size_t)r0 * HSZ + c0g) = make_float2(cs00, cs01);
                *(float2*)(cfin + (size_t)r1 * HSZ + c0g) = make_float2(cs10, cs11);
            }
        }

        if (t < T_STEPS - 1) flag_barrier((unsigned)(t + 1));
    }
#undef ISSUE
#undef BARG
}

// ---------------------------------------------------------------------------
extern "C" void kernel_launch(void* const* d_in, const int* in_sizes, int n_in,
                              void* d_out, int out_size)
{
    const float* x   = (const float*)d_in[0];
    const float* W0  = (const float*)d_in[1];
    const float* R0  = (const float*)d_in[2];
    const float* bi0 = (const float*)d_in[3];
    const float* bh0 = (const float*)d_in[4];
    const float* f0  = (const float*)d_in[5];
    const float* W1  = (const float*)d_in[6];
    const float* R1  = (const float*)d_in[7];
    const float* bi1 = (const float*)d_in[8];
    const float* bh1 = (const float*)d_in[9];
    const float* f1  = (const float*)d_in[10];
    float* out = (float*)d_out;

    float *gx, *h0;
    cudaGetSymbolAddress((void**)&gx, g_gx);
    cudaGetSymbolAddress((void**)&h0, g_h0);

    const int RSMEM = 49152 + 8 * 16384 + 18432;   // 198656 B
    cudaFuncSetAttribute(recurrent_kernel,
                         cudaFuncAttributeMaxDynamicSharedMemorySize, RSMEM);

    dim3 ggrid(G3 / 128, (T_STEPS * BATCH) / 128);   // (24, 256)

    // Layer 0
    gemm_tf32_kernel<<<ggrid, 256>>>(x, W0, bi0, bh0, gx);
    recurrent_kernel<<<NB, 512, RSMEM>>>(gx, R0, f0, h0,
                                         out + TBH,              // h0 final
                                         out + TBH + 2 * BH);    // c0 final
    // Layer 1
    gemm_tf32_kernel<<<ggrid, 256>>>(h0, W1, bi1, bh1, gx);
    recurrent_kernel<<<NB, 512, RSMEM>>>(gx, R1, f1, out,
                                         out + TBH + BH,         // h1 final
                                         out + TBH + 3 * BH);    // c1 final
}

// round 14
// speedup vs baseline: 1.3173x; 1.0093x over previous
#include <cuda_runtime.h>
#include <cuda_fp16.h>
#include <cstdint>

// SubLSTM: T=512, B=64, I=H=1024, L=2, gates (i,o,z), fixed forget fg=sigmoid(f)
//   gates = sigmoid(x W^T + h R^T + bi + bh)
//   c' = c*fg + z - i ;  h' = sigmoid(c') - o
// Output: [out (T*B*H)][h0_fin][h1_fin][c0_fin][c1_fin]

#define T_STEPS 512
#define BATCH   64
#define HSZ     1024
#define G3      3072
#define TBH     (T_STEPS * BATCH * HSZ)
#define BH      (BATCH * HSZ)
#define NB      128
#define HSLOTH  (HSZ * BATCH)        // 65536 halves per h slot

// Device-global scratch (allocation-free rule)
__device__ float  g_gx[(size_t)T_STEPS * BATCH * G3];   // [t][3072][64]
__device__ float  g_h0[(size_t)T_STEPS * BATCH * HSZ];  // [t][b][h] layer-0 out
// h ping-pong (2 slots), fp16, A-FRAGMENT order for m16n8k16:
//   half idx = kb*1024 + (b>>4)*256 + lane*8 + (hi*4 + hb8*2 + lo)
__device__ __half g_htrh[2 * HSLOTH];
__device__ unsigned g_arrive;                 // legacy atomic barrier (init only)
__device__ unsigned g_gen;
__device__ unsigned g_flags[NB * 32];         // per-CTA step flags, 128B stride

__device__ __forceinline__ float sigf(float x) { return 1.f / (1.f + __expf(-x)); }

// ===================== PTX helpers =====================
__device__ __forceinline__ uint32_t smem_u32(const void* p) {
    uint32_t a;
    asm("{ .reg .u64 t; cvta.to.shared.u64 t, %1; cvt.u32.u64 %0, t; }" : "=r"(a) : "l"(p));
    return a;
}
#define CP_ASYNC16(dst, src) \
    asm volatile("cp.async.ca.shared.global [%0], [%1], 16;" :: "r"(dst), "l"(src) : "memory")
#define CP_ASYNC_CG16(dst, src) \
    asm volatile("cp.async.cg.shared.global [%0], [%1], 16;" :: "r"(dst), "l"(src) : "memory")
#define CP_COMMIT() asm volatile("cp.async.commit_group;" ::: "memory")
#define CPWAIT(n)   asm volatile("cp.async.wait_group %0;" :: "n"(n) : "memory")

__device__ __forceinline__ unsigned ld_acq(const unsigned* p) {
    unsigned v;
    asm volatile("ld.acquire.gpu.u32 %0, [%1];" : "=r"(v) : "l"(p) : "memory");
    return v;
}
__device__ __forceinline__ void st_rel(unsigned* p, unsigned v) {
    asm volatile("st.release.gpu.u32 [%0], %1;" :: "l"(p), "r"(v) : "memory");
}

__device__ __forceinline__ uint32_t f2tf32(float x) {
    uint32_t u;
    asm("cvt.rna.tf32.f32 %0, %1;" : "=r"(u) : "f"(x));
    return u;
}
__device__ __forceinline__ void mma_tf32(float& d0, float& d1, float& d2, float& d3,
                                         uint32_t a0, uint32_t a1, uint32_t a2, uint32_t a3,
                                         uint32_t b0, uint32_t b1) {
    asm volatile("mma.sync.aligned.m16n8k8.row.col.f32.tf32.tf32.f32 "
                 "{%0,%1,%2,%3}, {%4,%5,%6,%7}, {%8,%9}, {%0,%1,%2,%3};"
                 : "+f"(d0), "+f"(d1), "+f"(d2), "+f"(d3)
                 : "r"(a0), "r"(a1), "r"(a2), "r"(a3), "r"(b0), "r"(b1));
}
__device__ __forceinline__ void mma_f16(float& d0, float& d1, float& d2, float& d3,
                                        uint32_t a0, uint32_t a1, uint32_t a2, uint32_t a3,
                                        uint32_t b0, uint32_t b1) {
    asm volatile("mma.sync.aligned.m16n8k16.row.col.f32.f16.f16.f32 "
                 "{%0,%1,%2,%3}, {%4,%5,%6,%7}, {%8,%9}, {%0,%1,%2,%3};"
                 : "+f"(d0), "+f"(d1), "+f"(d2), "+f"(d3)
                 : "r"(a0), "r"(a1), "r"(a2), "r"(a3), "r"(b0), "r"(b1));
}

// Legacy generation barrier (atomic). Used ONCE per launch to fence init.
__device__ __forceinline__ void grid_sync_atomic() {
    __threadfence();
    __syncthreads();
    if (threadIdx.x == 0) {
        unsigned gen = *(volatile unsigned*)&g_gen;
        unsigned t = atomicInc(&g_arrive, NB - 1);
        if (t == NB - 1) {
            __threadfence();
            *(volatile unsigned*)&g_gen = gen + 1;
        } else {
            while (*(volatile unsigned*)&g_gen == gen) { }
        }
        __threadfence();
    }
    __syncthreads();
}

// ---------------------------------------------------------------------------
// TF32 mma.sync GEMM (unchanged, passing)
// ---------------------------------------------------------------------------
#define SMPAD 36
__global__ __launch_bounds__(256, 2) void gemm_tf32_kernel(
    const float* __restrict__ A, const float* __restrict__ W,
    const float* __restrict__ bi, const float* __restrict__ bh,
    float* __restrict__ C)
{
    __shared__ float smA[128 * SMPAD];
    __shared__ float smB[128 * SMPAD];

    const int tid = threadIdx.x;
    const int wid = tid >> 5;
    const int lane = tid & 31;
    const int g   = lane >> 2;
    const int tig = lane & 3;
    const int wm  = wid & 3;
    const int wn  = wid >> 2;
    const int m0  = blockIdx.y * 128;
    const int n0  = blockIdx.x * 128;

    const uint32_t sa = smem_u32(smA);
    const uint32_t sb = smem_u32(smB);

    float acc[2][8][4];
#pragma unroll
    for (int mt = 0; mt < 2; mt++)
#pragma unroll
        for (int nt = 0; nt < 8; nt++)
#pragma unroll
            for (int r = 0; r < 4; r++) acc[mt][nt][r] = 0.f;

    const int lrow = tid >> 3;
    const int lq   = tid & 7;

#pragma unroll 1
    for (int kt = 0; kt < HSZ / 32; kt++) {
        const int k0 = kt * 32;
#pragma unroll
        for (int i = 0; i < 4; i++) {
            const int row = lrow + i * 32;
            CP_ASYNC16(sa + (uint32_t)(row * SMPAD + lq * 4) * 4,
                       A + (size_t)(m0 + row) * HSZ + k0 + lq * 4);
            CP_ASYNC16(sb + (uint32_t)(row * SMPAD + lq * 4) * 4,
                       W + (size_t)(n0 + row) * HSZ + k0 + lq * 4);
        }
        CP_COMMIT();
        CPWAIT(0);
        __syncthreads();

#pragma unroll
        for (int s = 0; s < 4; s++) {
            const int kc = s * 8 + tig;
            uint32_t af[2][4];
#pragma unroll
            for (int mt = 0; mt < 2; mt++) {
                const int r0 = (wm * 32 + mt * 16 + g) * SMPAD;
                af[mt][0] = f2tf32(smA[r0 + kc]);
                af[mt][1] = f2tf32(smA[r0 + 8 * SMPAD + kc]);
                af[mt][2] = f2tf32(smA[r0 + kc + 4]);
                af[mt][3] = f2tf32(smA[r0 + 8 * SMPAD + kc + 4]);
            }
#pragma unroll
            for (int nt = 0; nt < 8; nt++) {
                const int nr = (wn * 64 + nt * 8 + g) * SMPAD;
                uint32_t b0 = f2tf32(smB[nr + kc]);
                uint32_t b1 = f2tf32(smB[nr + kc + 4]);
#pragma unroll
                for (int mt = 0; mt < 2; mt++)
                    mma_tf32(acc[mt][nt][0], acc[mt][nt][1], acc[mt][nt][2], acc[mt][nt][3],
                             af[mt][0], af[mt][1], af[mt][2], af[mt][3], b0, b1);
            }
        }
        __syncthreads();
    }

    float* stage = smA;
    const int m_lane = tid & 63;
    const int n_off  = tid >> 6;
#pragma unroll 1
    for (int ci = 0; ci < 4; ci++) {
        if (wn == (ci >> 1)) {
            const int ntb = (ci & 1) * 4;
#pragma unroll
            for (int mt = 0; mt < 2; mt++) {
                const int r0 = wm * 32 + mt * 16 + g;
#pragma unroll
                for (int nn = 0; nn < 4; nn++) {
                    const int nt = ntb + nn;
                    const int nl = nn * 8 + 2 * tig;
                    stage[r0 * 33 + nl]           = acc[mt][nt][0];
                    stage[r0 * 33 + nl + 1]       = acc[mt][nt][1];
                    stage[(r0 + 8) * 33 + nl]     = acc[mt][nt][2];
                    stage[(r0 + 8) * 33 + nl + 1] = acc[mt][nt][3];
                }
            }
        }
        __syncthreads();
#pragma unroll
        for (int p = 0; p < 8; p++) {
            const int nlc = p * 4 + n_off;
            const int ng  = n0 + ci * 32 + nlc;
            const float bias = __ldg(bi + ng) + __ldg(bh + ng);
#pragma unroll
            for (int half = 0; half < 2; half++) {
                const int m  = m_lane + half * 64;
                const int mg = m0 + m;
                C[((size_t)(mg >> 6) * G3 + ng) * BATCH + (mg & 63)] =
                    stage[m * 33 + nlc] + bias;
            }
        }
        __syncthreads();
    }
}

// ---------------------------------------------------------------------------
// Persistent fp16 MMA recurrence: 128 CTAs x 512 threads = 4 warp-groups.
// Group g owns K-chunks 2g, 2g+1 (2-buf cp.async pipeline, named barrier
// grp+1). Partials reduced via smem scratch into group 0 (one sync).
// EARLY RELEASE: grp0 stores the h slot, syncs only grp0 (named bar), tid0
// releases the step flag; hb/final stores happen after the release. Groups
// 1-3 skip the epilogue and poll immediately.
// Smem: R 48KB + 8 x 16KB A bufs + 18KB scratch = 198.5KB.
// ---------------------------------------------------------------------------
__global__ __launch_bounds__(512) void recurrent_kernel(
    const float* __restrict__ gx,   // [T][3072][64]
    const float* __restrict__ R,    // [3072][1024]
    const float* __restrict__ f,    // [1024]
    float* __restrict__ hb,         // [T][B][H]
    float* __restrict__ hfin,       // [B][H]
    float* __restrict__ cfin)       // [B][H]
{
    extern __shared__ __align__(16) char s_dyn[];
    __half* Rsh = (__half*)s_dyn;               // 49152 B (B-frag order)
    char*   Asm = s_dyn + 49152;                // 8 bufs x 16384 B
    float*  red = (float*)(s_dyn + 49152 + 131072);  // 18432 B scratch

    const int tid  = threadIdx.x;
    const int wid  = tid >> 5;
    const int grp  = wid >> 2;          // warp-group 0..3
    const int wm   = wid & 3;
    const int gtid = tid & 127;
    const int lane = tid & 31;
    const int g    = lane >> 2;
    const int tig  = lane & 3;
    const int bid  = blockIdx.x;
    const int colbase = bid * 8;
    const int gb   = grp * 2;           // first global chunk of this group

    if (tid == 0) g_flags[bid * 32] = 0;

    // ---- Load R slice -> B-fragment-order fp16 smem, once ----
    for (int v = tid; v < 6144; v += 512) {
        const int n  = v >> 8;
        const int k  = (v & 255) * 4;
        const int nt = n >> 3, nloc = n & 7;
        const int row = nt * HSZ + colbase + nloc;
        float4 w = *(const float4*)(R + (size_t)row * HSZ + k);
        const int kb = k >> 4, kin = k & 15;
        const int t0 = (kin & 7) >> 1;
        const int hi = kin >> 3;
        __half* base = Rsh + (((kb * 3 + nt) * 32 + nloc * 4) * 4 + hi * 2);
        *(__half2*)(base + (t0    ) * 4) = __floats2half2_rn(w.x, w.y);
        *(__half2*)(base + (t0 + 1) * 4) = __floats2half2_rn(w.z, w.w);
    }

    grid_sync_atomic();   // flag resets + R smem visible/done

    const int r0 = wm * 16 + g;
    const int r1 = r0 + 8;
    const int c0g = colbase + 2 * tig;
    const int c1g = c0g + 1;
    const float fg0 = sigf(__ldg(f + c0g));
    const float fg1 = sigf(__ldg(f + c1g));
    float cs00 = 0.f, cs01 = 0.f, cs10 = 0.f, cs11 = 0.f;

    const uint32_t hsA  = smem_u32(Asm);
    const uint32_t grpb = (uint32_t)grp * 2 * 16384;
    const uint32_t a_lm = hsA + grpb + (uint32_t)(wm * 512 + lane * 16);
    const int wp = (colbase >> 4) * 1024 + wm * 256 + lane * 8
                 + ((colbase >> 3) & 1) * 4;

#define BARG() asm volatile("bar.sync %0, 128;" :: "r"(grp + 1) : "memory")
#define ISSUE(cglob, buf) do {                                                   \
        const char* s_ = (const char*)hsrc + (size_t)(cglob) * 16384 + gtid * 16; \
        uint32_t d_ = hsA + grpb + (uint32_t)(buf) * 16384 + (uint32_t)(gtid * 16); \
        _Pragma("unroll")                                                        \
        for (int j_ = 0; j_ < 8; j_++)                                           \
            CP_ASYNC_CG16(d_ + j_ * 2048, s_ + j_ * 2048);                       \
        CP_COMMIT();                                                             \
    } while (0)

#pragma unroll 1
    for (int t = 0; t < T_STEPS; t++) {
        // gx preactivations (group 0 only; early issue, consumed in epilogue)
        float xi00 = 0.f, xi01 = 0.f, xi10 = 0.f, xi11 = 0.f;
        float xo00 = 0.f, xo01 = 0.f, xo10 = 0.f, xo11 = 0.f;
        float xz00 = 0.f, xz01 = 0.f, xz10 = 0.f, xz11 = 0.f;
        if (grp == 0) {
            const float* gxt = gx + (size_t)t * G3 * BATCH;
            xi00 = __ldcg(gxt + (size_t)c0g * BATCH + r0);
            xi01 = __ldcg(gxt + (size_t)c1g * BATCH + r0);
            xi10 = __ldcg(gxt + (size_t)c0g * BATCH + r1);
            xi11 = __ldcg(gxt + (size_t)c1g * BATCH + r1);
            xo00 = __ldcg(gxt + (size_t)(HSZ + c0g) * BATCH + r0);
            xo01 = __ldcg(gxt + (size_t)(HSZ + c1g) * BATCH + r0);
            xo10 = __ldcg(gxt + (size_t)(HSZ + c0g) * BATCH + r1);
            xo11 = __ldcg(gxt + (size_t)(HSZ + c1g) * BATCH + r1);
            xz00 = __ldcg(gxt + (size_t)(2 * HSZ + c0g) * BATCH + r0);
            xz01 = __ldcg(gxt + (size_t)(2 * HSZ + c1g) * BATCH + r0);
            xz10 = __ldcg(gxt + (size_t)(2 * HSZ + c0g) * BATCH + r1);
            xz11 = __ldcg(gxt + (size_t)(2 * HSZ + c1g) * BATCH + r1);
        }

        float a[3][4] = {{0.f,0.f,0.f,0.f},{0.f,0.f,0.f,0.f},{0.f,0.f,0.f,0.f}};

        if (t > 0) {
            const __half* hsrc = g_htrh + (size_t)((t - 1) & 1) * HSLOTH;
            ISSUE(gb + 0, 0);
            ISSUE(gb + 1, 1);
#pragma unroll
            for (int l = 0; l < 2; l++) {
                if (l == 0) CPWAIT(1); else CPWAIT(0);
                BARG();                  // chunk l landed group-wide
                const uint32_t a_ch = a_lm + (uint32_t)l * 16384;
#pragma unroll
                for (int blk = 0; blk < 8; blk++) {
                    uint4 Af;
                    asm volatile("ld.shared.v4.b32 {%0,%1,%2,%3}, [%4];"
                                 : "=r"(Af.x), "=r"(Af.y), "=r"(Af.z), "=r"(Af.w)
                                 : "r"(a_ch + (uint32_t)(blk * 2048)));
                    const int kbg = (gb + l) * 8 + blk;
                    const uint2* bf = (const uint2*)((const char*)Rsh
                                      + (size_t)(kbg * 3) * 256 + lane * 8);
#pragma unroll
                    for (int nt = 0; nt < 3; nt++) {
                        const uint2 Bf = bf[nt * 32];
                        mma_f16(a[nt][0], a[nt][1], a[nt][2], a[nt][3],
                                Af.x, Af.y, Af.z, Af.w, Bf.x, Bf.y);
                    }
                }
            }
            // ---- reduce groups 1-3 partials into group 0 ----
            // (WAR on red vs grp0's reads of step t-1 is ordered by the
            //  inter-step barrier's trailing __syncthreads.)
            if (grp > 0) {
                float* d = red + (size_t)(grp - 1) * 1536 + gtid * 12;
#pragma unroll
                for (int nt = 0; nt < 3; nt++)
#pragma unroll
                    for (int r = 0; r < 4; r++) d[nt * 4 + r] = a[nt][r];
            }
            __syncthreads();
            if (grp == 0) {
#pragma unroll
                for (int s = 0; s < 3; s++) {
                    const float* sp = red + (size_t)s * 1536 + gtid * 12;
#pragma unroll
                    for (int nt = 0; nt < 3; nt++)
#pragma unroll
                        for (int r = 0; r < 4; r++) a[nt][r] += sp[nt * 4 + r];
                }
            }
        }

        // ---- epilogue (group 0): gates, cell, h-slot store, EARLY release ----
        if (grp == 0) {
            const float i00 = sigf(a[0][0] + xi00), i01 = sigf(a[0][1] + xi01);
            const float i10 = sigf(a[0][2] + xi10), i11 = sigf(a[0][3] + xi11);
            const float o00 = sigf(a[1][0] + xo00), o01 = sigf(a[1][1] + xo01);
            const float o10 = sigf(a[1][2] + xo10), o11 = sigf(a[1][3] + xo11);
            const float z00 = sigf(a[2][0] + xz00), z01 = sigf(a[2][1] + xz01);
            const float z10 = sigf(a[2][2] + xz10), z11 = sigf(a[2][3] + xz11);

            cs00 = cs00 * fg0 + z00 - i00;
            cs01 = cs01 * fg1 + z01 - i01;
            cs10 = cs10 * fg0 + z10 - i10;
            cs11 = cs11 * fg1 + z11 - i11;
            const float h00 = sigf(cs00) - o00;
            const float h01 = sigf(cs01) - o01;
            const float h10 = sigf(cs10) - o10;
            const float h11 = sigf(cs11) - o11;

            // h -> fp16 A-fragment ping-pong (consumed by peers next step)
            {
                __half2 p0 = __floats2half2_rn(h00, h01);
                __half2 p1 = __floats2half2_rn(h10, h11);
                uint2 pk;
                pk.x = *(unsigned*)&p0;
                pk.y = *(unsigned*)&p1;
                __half* slot = g_htrh + (size_t)(t & 1) * HSLOTH + wp;
                __stcg((uint2*)slot, pk);
            }

            // EARLY RELEASE: only grp0's 128 threads need to have stored.
            if (t < T_STEPS - 1) {
                BARG();                          // bar.sync 1,128 (grp0)
                if (tid == 0) st_rel(&g_flags[bid * 32], (unsigned)(t + 1));
            }

            // Non-consumed outputs after the release.
            float* hbt = hb + (size_t)t * BH;
            __stcg((float2*)(hbt + (size_t)r0 * HSZ + c0g), make_float2(h00, h01));
            __stcg((float2*)(hbt + (size_t)r1 * HSZ + c0g), make_float2(h10, h11));

            if (t == T_STEPS - 1) {
                *(float2*)(hfin + (size_t)r0 * HSZ + c0g) = make_float2(h00, h01);
                *(float2*)(hfin + (size_t)r1 * HSZ + c0g) = make_float2(h10, h11);
                *(float2*)(cfin + (size_t)r0 * HSZ + c0g) = make_float2(cs00, cs01);
                *(float2*)(cfin + (size_t)r1 * HSZ + c0g) = make_float2(cs10, cs11);
            }
        }

        // ---- inter-step barrier: poll peers' flags, then CTA-wide sync ----
        if (t < T_STEPS - 1) {
            if (tid < NB) {
                const unsigned val = (unsigned)(t + 1);
                while (ld_acq(&g_flags[tid * 32]) < val) { }
            }
            __syncthreads();
        }
    }
#undef ISSUE
#undef BARG
}

// ---------------------------------------------------------------------------
extern "C" void kernel_launch(void* const* d_in, const int* in_sizes, int n_in,
                              void* d_out, int out_size)
{
    const float* x   = (const float*)d_in[0];
    const float* W0  = (const float*)d_in[1];
    const float* R0  = (const float*)d_in[2];
    const float* bi0 = (const float*)d_in[3];
    const float* bh0 = (const float*)d_in[4];
    const float* f0  = (const float*)d_in[5];
    const float* W1  = (const float*)d_in[6];
    const float* R1  = (const float*)d_in[7];
    const float* bi1 = (const float*)d_in[8];
    const float* bh1 = (const float*)d_in[9];
    const float* f1  = (const float*)d_in[10];
    float* out = (float*)d_out;

    float *gx, *h0;
    cudaGetSymbolAddress((void**)&gx, g_gx);
    cudaGetSymbolAddress((void**)&h0, g_h0);

    const int RSMEM = 49152 + 8 * 16384 + 18432;   // 198656 B
    cudaFuncSetAttribute(recurrent_kernel,
                         cudaFuncAttributeMaxDynamicSharedMemorySize, RSMEM);

    dim3 ggrid(G3 / 128, (T_STEPS * BATCH) / 128);   // (24, 256)

    // Layer 0
    gemm_tf32_kernel<<<ggrid, 256>>>(x, W0, bi0, bh0, gx);
    recurrent_kernel<<<NB, 512, RSMEM>>>(gx, R0, f0, h0,
                                         out + TBH,              // h0 final
                                         out + TBH + 2 * BH);    // c0 final
    // Layer 1
    gemm_tf32_kernel<<<ggrid, 256>>>(h0, W1, bi1, bh1, gx);
    recurrent_kernel<<<NB, 512, RSMEM>>>(gx, R1, f1, out,
                                         out + TBH + BH,         // h1 final
                                         out + TBH + 3 * BH);    // c1 final
}

// round 15
// speedup vs baseline: 2.0554x; 1.5603x over previous
#include <cuda_runtime.h>
#include <cuda_fp16.h>
#include <cstdint>

// SubLSTM: T=512, B=64, I=H=1024, L=2, gates (i,o,z), fixed forget fg=sigmoid(f)
//   gates = sigmoid(x W^T + h R^T + bi + bh)
//   c' = c*fg + z - i ;  h' = sigmoid(c') - o
// Output: [out (T*B*H)][h0_fin][h1_fin][c0_fin][c1_fin]
//
// FUSED: one persistent kernel runs both layers; stage s does layer0 step s
// and layer1 step s-1 (gates1 accumulates W1@h0 and R1@h1 in one fp32 acc).

#define T_STEPS 512
#define BATCH   64
#define HSZ     1024
#define G3      3072
#define TBH     (T_STEPS * BATCH * HSZ)
#define BH      (BATCH * HSZ)
#define NB      128
#define HSLOTH  (HSZ * BATCH)        // 65536 halves per h slot

// Device-global scratch (allocation-free rule)
__device__ float  g_gx[(size_t)T_STEPS * BATCH * G3];   // [t][3072][64] layer0 Wx+b
// h ping-pong slots, fp16, A-FRAGMENT order for m16n8k16:
//   half idx = kb*1024 + (b>>4)*256 + lane*8 + (hi*4 + hb8*2 + lo)
__device__ __half g_h0s[2 * HSLOTH];
__device__ __half g_h1s[2 * HSLOTH];
__device__ unsigned g_arrive;                 // legacy atomic barrier (init only)
__device__ unsigned g_gen;
__device__ unsigned g_flags[NB * 32];         // per-CTA stage flags, 128B stride

__device__ __forceinline__ float sigf(float x) { return 1.f / (1.f + __expf(-x)); }

// ===================== PTX helpers =====================
__device__ __forceinline__ uint32_t smem_u32(const void* p) {
    uint32_t a;
    asm("{ .reg .u64 t; cvta.to.shared.u64 t, %1; cvt.u32.u64 %0, t; }" : "=r"(a) : "l"(p));
    return a;
}
#define CP_ASYNC16(dst, src) \
    asm volatile("cp.async.ca.shared.global [%0], [%1], 16;" :: "r"(dst), "l"(src) : "memory")
#define CP_ASYNC_CG16(dst, src) \
    asm volatile("cp.async.cg.shared.global [%0], [%1], 16;" :: "r"(dst), "l"(src) : "memory")
#define CP_COMMIT() asm volatile("cp.async.commit_group;" ::: "memory")
#define CPWAIT(n)   asm volatile("cp.async.wait_group %0;" :: "n"(n) : "memory")

__device__ __forceinline__ unsigned ld_acq(const unsigned* p) {
    unsigned v;
    asm volatile("ld.acquire.gpu.u32 %0, [%1];" : "=r"(v) : "l"(p) : "memory");
    return v;
}
__device__ __forceinline__ void st_rel(unsigned* p, unsigned v) {
    asm volatile("st.release.gpu.u32 [%0], %1;" :: "l"(p), "r"(v) : "memory");
}

__device__ __forceinline__ uint32_t f2tf32(float x) {
    uint32_t u;
    asm("cvt.rna.tf32.f32 %0, %1;" : "=r"(u) : "f"(x));
    return u;
}
__device__ __forceinline__ void mma_tf32(float& d0, float& d1, float& d2, float& d3,
                                         uint32_t a0, uint32_t a1, uint32_t a2, uint32_t a3,
                                         uint32_t b0, uint32_t b1) {
    asm volatile("mma.sync.aligned.m16n8k8.row.col.f32.tf32.tf32.f32 "
                 "{%0,%1,%2,%3}, {%4,%5,%6,%7}, {%8,%9}, {%0,%1,%2,%3};"
                 : "+f"(d0), "+f"(d1), "+f"(d2), "+f"(d3)
                 : "r"(a0), "r"(a1), "r"(a2), "r"(a3), "r"(b0), "r"(b1));
}
__device__ __forceinline__ void mma_f16(float& d0, float& d1, float& d2, float& d3,
                                        uint32_t a0, uint32_t a1, uint32_t a2, uint32_t a3,
                                        uint32_t b0, uint32_t b1) {
    asm volatile("mma.sync.aligned.m16n8k16.row.col.f32.f16.f16.f32 "
                 "{%0,%1,%2,%3}, {%4,%5,%6,%7}, {%8,%9}, {%0,%1,%2,%3};"
                 : "+f"(d0), "+f"(d1), "+f"(d2), "+f"(d3)
                 : "r"(a0), "r"(a1), "r"(a2), "r"(a3), "r"(b0), "r"(b1));
}

// Legacy generation barrier (atomic). Used ONCE per launch to fence init.
__device__ __forceinline__ void grid_sync_atomic() {
    __threadfence();
    __syncthreads();
    if (threadIdx.x == 0) {
        unsigned gen = *(volatile unsigned*)&g_gen;
        unsigned t = atomicInc(&g_arrive, NB - 1);
        if (t == NB - 1) {
            __threadfence();
            *(volatile unsigned*)&g_gen = gen + 1;
        } else {
            while (*(volatile unsigned*)&g_gen == gen) { }
        }
        __threadfence();
    }
    __syncthreads();
}

// ---------------------------------------------------------------------------
// TF32 mma.sync GEMM (unchanged, passing) -- used for layer-0 input gates only
// ---------------------------------------------------------------------------
#define SMPAD 36
__global__ __launch_bounds__(256, 2) void gemm_tf32_kernel(
    const float* __restrict__ A, const float* __restrict__ W,
    const float* __restrict__ bi, const float* __restrict__ bh,
    float* __restrict__ C)
{
    __shared__ float smA[128 * SMPAD];
    __shared__ float smB[128 * SMPAD];

    const int tid = threadIdx.x;
    const int wid = tid >> 5;
    const int lane = tid & 31;
    const int g   = lane >> 2;
    const int tig = lane & 3;
    const int wm  = wid & 3;
    const int wn  = wid >> 2;
    const int m0  = blockIdx.y * 128;
    const int n0  = blockIdx.x * 128;

    const uint32_t sa = smem_u32(smA);
    const uint32_t sb = smem_u32(smB);

    float acc[2][8][4];
#pragma unroll
    for (int mt = 0; mt < 2; mt++)
#pragma unroll
        for (int nt = 0; nt < 8; nt++)
#pragma unroll
            for (int r = 0; r < 4; r++) acc[mt][nt][r] = 0.f;

    const int lrow = tid >> 3;
    const int lq   = tid & 7;

#pragma unroll 1
    for (int kt = 0; kt < HSZ / 32; kt++) {
        const int k0 = kt * 32;
#pragma unroll
        for (int i = 0; i < 4; i++) {
            const int row = lrow + i * 32;
            CP_ASYNC16(sa + (uint32_t)(row * SMPAD + lq * 4) * 4,
                       A + (size_t)(m0 + row) * HSZ + k0 + lq * 4);
            CP_ASYNC16(sb + (uint32_t)(row * SMPAD + lq * 4) * 4,
                       W + (size_t)(n0 + row) * HSZ + k0 + lq * 4);
        }
        CP_COMMIT();
        CPWAIT(0);
        __syncthreads();

#pragma unroll
        for (int s = 0; s < 4; s++) {
            const int kc = s * 8 + tig;
            uint32_t af[2][4];
#pragma unroll
            for (int mt = 0; mt < 2; mt++) {
                const int r0 = (wm * 32 + mt * 16 + g) * SMPAD;
                af[mt][0] = f2tf32(smA[r0 + kc]);
                af[mt][1] = f2tf32(smA[r0 + 8 * SMPAD + kc]);
                af[mt][2] = f2tf32(smA[r0 + kc + 4]);
                af[mt][3] = f2tf32(smA[r0 + 8 * SMPAD + kc + 4]);
            }
#pragma unroll
            for (int nt = 0; nt < 8; nt++) {
                const int nr = (wn * 64 + nt * 8 + g) * SMPAD;
                uint32_t b0 = f2tf32(smB[nr + kc]);
                uint32_t b1 = f2tf32(smB[nr + kc + 4]);
#pragma unroll
                for (int mt = 0; mt < 2; mt++)
                    mma_tf32(acc[mt][nt][0], acc[mt][nt][1], acc[mt][nt][2], acc[mt][nt][3],
                             af[mt][0], af[mt][1], af[mt][2], af[mt][3], b0, b1);
            }
        }
        __syncthreads();
    }

    float* stage = smA;
    const int m_lane = tid & 63;
    const int n_off  = tid >> 6;
#pragma unroll 1
    for (int ci = 0; ci < 4; ci++) {
        if (wn == (ci >> 1)) {
            const int ntb = (ci & 1) * 4;
#pragma unroll
            for (int mt = 0; mt < 2; mt++) {
                const int r0 = wm * 32 + mt * 16 + g;
#pragma unroll
                for (int nn = 0; nn < 4; nn++) {
                    const int nt = ntb + nn;
                    const int nl = nn * 8 + 2 * tig;
                    stage[r0 * 33 + nl]           = acc[mt][nt][0];
                    stage[r0 * 33 + nl + 1]       = acc[mt][nt][1];
                    stage[(r0 + 8) * 33 + nl]     = acc[mt][nt][2];
                    stage[(r0 + 8) * 33 + nl + 1] = acc[mt][nt][3];
                }
            }
        }
        __syncthreads();
#pragma unroll
        for (int p = 0; p < 8; p++) {
            const int nlc = p * 4 + n_off;
            const int ng  = n0 + ci * 32 + nlc;
            const float bias = __ldg(bi + ng) + __ldg(bh + ng);
#pragma unroll
            for (int half = 0; half < 2; half++) {
                const int m  = m_lane + half * 64;
                const int mg = m0 + m;
                C[((size_t)(mg >> 6) * G3 + ng) * BATCH + (mg & 63)] =
                    stage[m * 33 + nlc] + bias;
            }
        }
        __syncthreads();
    }
}

// ---------------------------------------------------------------------------
// Fused persistent recurrence: 128 CTAs x 256 threads = 2 warp-groups.
// Stage s: layer0 step s (R0@h0_{s-1} + gx0[s]) and layer1 step s-1
// (W1@h0_{s-1} + R1@h1_{s-2} + bias1), 513 stages.
// Group g owns K-half [512g,512g+512) of BOTH h0 and h1: 8 chunk iterations
// (4 h0 + 4 h1) on 2x16KB bufs. h0 A-fragments feed both R0 and W1 MMAs.
// grp0: layer0 reduce+epilogue; grp1: layer1 reduce+epilogue (+ out stores).
// Weights R0/W1/R1 resident in B-fragment order (48KB each).
// Smem: 144KB weights + 2 grp x 2 x 16KB bufs + 12KB scratch = 220KB.
// ---------------------------------------------------------------------------
__global__ __launch_bounds__(256) void fused_kernel(
    const float* __restrict__ gx,   // [T][3072][64] layer0 input gates
    const float* __restrict__ R0,
    const float* __restrict__ f0,
    const float* __restrict__ W1,
    const float* __restrict__ R1,
    const float* __restrict__ bi1,
    const float* __restrict__ bh1,
    const float* __restrict__ f1,
    float* __restrict__ out)        // [T*B*H][h0f][h1f][c0f][c1f]
{
    extern __shared__ __align__(16) char s_dyn[];
    __half* Rsh = (__half*)s_dyn;               // 3 x 49152 B (R0, W1, R1)
    char*   Asm = s_dyn + 147456;               // 2 grp x 2 bufs x 16384 B
    float*  red = (float*)(s_dyn + 147456 + 65536);  // 12288 B scratch

    const int tid  = threadIdx.x;
    const int wid  = tid >> 5;
    const int grp  = wid >> 2;          // warp-group 0/1
    const int wm   = wid & 3;
    const int gtid = tid & 127;
    const int lane = tid & 31;
    const int g    = lane >> 2;
    const int tig  = lane & 3;
    const int bid  = blockIdx.x;
    const int colbase = bid * 8;
    const int gb   = grp * 4;           // first chunk (of 8) of this group

    if (tid == 0) g_flags[bid * 32] = 0;

    // ---- Load R0, W1, R1 slices -> B-fragment-order fp16 smem, once ----
    {
        const float* Ws[3] = {R0, W1, R1};
#pragma unroll 1
        for (int m = 0; m < 3; m++) {
            __half* dst0 = Rsh + (size_t)m * 24576;
            for (int v = tid; v < 6144; v += 256) {
                const int n  = v >> 8;
                const int k  = (v & 255) * 4;
                const int nt = n >> 3, nloc = n & 7;
                const int row = nt * HSZ + colbase + nloc;
                float4 w = *(const float4*)(Ws[m] + (size_t)row * HSZ + k);
                const int kb = k >> 4, kin = k & 15;
                const int t0 = (kin & 7) >> 1;
                const int hi = kin >> 3;
                __half* base = dst0 + (((kb * 3 + nt) * 32 + nloc * 4) * 4 + hi * 2);
                *(__half2*)(base + (t0    ) * 4) = __floats2half2_rn(w.x, w.y);
                *(__half2*)(base + (t0 + 1) * 4) = __floats2half2_rn(w.z, w.w);
            }
        }
    }

    grid_sync_atomic();   // flag resets + weights visible/done

    const int r0 = wm * 16 + g;
    const int r1 = r0 + 8;
    const int c0g = colbase + 2 * tig;
    const int c1g = c0g + 1;
    // per-group constants
    const float* fsrc = (grp == 0) ? f0 : f1;
    const float fga = sigf(__ldg(fsrc + c0g));
    const float fgb = sigf(__ldg(fsrc + c1g));
    float cs00 = 0.f, cs01 = 0.f, cs10 = 0.f, cs11 = 0.f;   // own layer's cell
    // layer1 biases (grp1 only)
    float bI0 = 0.f, bI1 = 0.f, bO0 = 0.f, bO1 = 0.f, bZ0 = 0.f, bZ1 = 0.f;
    if (grp == 1) {
        bI0 = __ldg(bi1 + c0g) + __ldg(bh1 + c0g);
        bI1 = __ldg(bi1 + c1g) + __ldg(bh1 + c1g);
        bO0 = __ldg(bi1 + HSZ + c0g) + __ldg(bh1 + HSZ + c0g);
        bO1 = __ldg(bi1 + HSZ + c1g) + __ldg(bh1 + HSZ + c1g);
        bZ0 = __ldg(bi1 + 2 * HSZ + c0g) + __ldg(bh1 + 2 * HSZ + c0g);
        bZ1 = __ldg(bi1 + 2 * HSZ + c1g) + __ldg(bh1 + 2 * HSZ + c1g);
    }

    const uint32_t hsA  = smem_u32(Asm);
    const uint32_t grpb = (uint32_t)grp * 2 * 16384;
    const uint32_t a_lm = hsA + grpb + (uint32_t)(wm * 512 + lane * 16);
    const int wp = (colbase >> 4) * 1024 + wm * 256 + lane * 8
                 + ((colbase >> 3) & 1) * 4;

#define BARG() asm volatile("bar.sync %0, 128;" :: "r"(grp + 1) : "memory")
#define ISSUEF(srcp, cidx, buf) do {                                             \
        const char* s_ = (const char*)(srcp) + (size_t)(cidx) * 16384 + gtid * 16; \
        uint32_t d_ = hsA + grpb + (uint32_t)(buf) * 16384 + (uint32_t)(gtid * 16); \
        _Pragma("unroll")                                                        \
        for (int j_ = 0; j_ < 8; j_++)                                           \
            CP_ASYNC_CG16(d_ + j_ * 2048, s_ + j_ * 2048);                       \
        CP_COMMIT();                                                             \
    } while (0)

#pragma unroll 1
    for (int s = 0; s <= T_STEPS; s++) {
        // layer0 gx preactivations (grp0 only; early issue)
        float xi00 = 0.f, xi01 = 0.f, xi10 = 0.f, xi11 = 0.f;
        float xo00 = 0.f, xo01 = 0.f, xo10 = 0.f, xo11 = 0.f;
        float xz00 = 0.f, xz01 = 0.f, xz10 = 0.f, xz11 = 0.f;
        if (grp == 0 && s < T_STEPS) {
            const float* gxt = gx + (size_t)s * G3 * BATCH;
            xi00 = __ldcg(gxt + (size_t)c0g * BATCH + r0);
            xi01 = __ldcg(gxt + (size_t)c1g * BATCH + r0);
            xi10 = __ldcg(gxt + (size_t)c0g * BATCH + r1);
            xi11 = __ldcg(gxt + (size_t)c1g * BATCH + r1);
            xo00 = __ldcg(gxt + (size_t)(HSZ + c0g) * BATCH + r0);
            xo01 = __ldcg(gxt + (size_t)(HSZ + c1g) * BATCH + r0);
            xo10 = __ldcg(gxt + (size_t)(HSZ + c0g) * BATCH + r1);
            xo11 = __ldcg(gxt + (size_t)(HSZ + c1g) * BATCH + r1);
            xz00 = __ldcg(gxt + (size_t)(2 * HSZ + c0g) * BATCH + r0);
            xz01 = __ldcg(gxt + (size_t)(2 * HSZ + c1g) * BATCH + r0);
            xz10 = __ldcg(gxt + (size_t)(2 * HSZ + c0g) * BATCH + r1);
            xz11 = __ldcg(gxt + (size_t)(2 * HSZ + c1g) * BATCH + r1);
        }

        float a0[3][4], a1[3][4];
#pragma unroll
        for (int nt = 0; nt < 3; nt++)
#pragma unroll
            for (int r = 0; r < 4; r++) { a0[nt][r] = 0.f; a1[nt][r] = 0.f; }

        if (s >= 1) {
            const __half* h0src = g_h0s + (size_t)((s - 1) & 1) * HSLOTH;
            const __half* h1src = g_h1s + (size_t)(s & 1) * HSLOTH;
            const bool use_r0 = (s < T_STEPS);
            const bool use_r1 = (s >= 2);
            ISSUEF(h0src, gb + 0, 0);
            ISSUEF(h0src, gb + 1, 1);
#pragma unroll
            for (int l = 0; l < 8; l++) {
                if (l == 7) CPWAIT(0); else CPWAIT(1);
                BARG();                  // chunk l landed group-wide
                const uint32_t a_ch = a_lm + (uint32_t)(l & 1) * 16384;
                const int cloc = (l < 4) ? (gb + l) : (gb + l - 4);
#pragma unroll
                for (int blk = 0; blk < 8; blk++) {
                    uint4 Af;
                    asm volatile("ld.shared.v4.b32 {%0,%1,%2,%3}, [%4];"
                                 : "=r"(Af.x), "=r"(Af.y), "=r"(Af.z), "=r"(Af.w)
                                 : "r"(a_ch + (uint32_t)(blk * 2048)));
                    const int kbg = cloc * 8 + blk;
                    const char* wb = (const char*)Rsh + (size_t)kbg * 768 + lane * 8;
                    if (l < 4) {
                        if (use_r0) {
                            const uint2* bf = (const uint2*)wb;        // R0
#pragma unroll
                            for (int nt = 0; nt < 3; nt++) {
                                const uint2 Bf = bf[nt * 32];
                                mma_f16(a0[nt][0], a0[nt][1], a0[nt][2], a0[nt][3],
                                        Af.x, Af.y, Af.z, Af.w, Bf.x, Bf.y);
                            }
                        }
                        {
                            const uint2* bf = (const uint2*)(wb + 49152);  // W1
#pragma unroll
                            for (int nt = 0; nt < 3; nt++) {
                                const uint2 Bf = bf[nt * 32];
                                mma_f16(a1[nt][0], a1[nt][1], a1[nt][2], a1[nt][3],
                                        Af.x, Af.y, Af.z, Af.w, Bf.x, Bf.y);
                            }
                        }
                    } else {
                        if (use_r1) {
                            const uint2* bf = (const uint2*)(wb + 98304);  // R1
#pragma unroll
                            for (int nt = 0; nt < 3; nt++) {
                                const uint2 Bf = bf[nt * 32];
                                mma_f16(a1[nt][0], a1[nt][1], a1[nt][2], a1[nt][3],
                                        Af.x, Af.y, Af.z, Af.w, Bf.x, Bf.y);
                            }
                        }
                    }
                }
                if (l + 2 <= 7) {
                    BARG();              // compute done, buf l&1 reusable
                    const __half* nsrc = (l + 2 < 4) ? h0src : h1src;
                    const int nc = (l + 2 < 4) ? (gb + l + 2) : (gb + l - 2);
                    ISSUEF(nsrc, nc, (l & 1));
                }
            }
        }

        // ---- exchange partials: grp0 gives a1, grp1 gives a0 ----
        // (WAR on red vs prior stage protected by inter-stage barrier sync)
        {
            float* d = red + (size_t)grp * 1536 + gtid * 12;
            if (grp == 0) {
#pragma unroll
                for (int nt = 0; nt < 3; nt++)
#pragma unroll
                    for (int r = 0; r < 4; r++) d[nt * 4 + r] = a1[nt][r];
            } else {
#pragma unroll
                for (int nt = 0; nt < 3; nt++)
#pragma unroll
                    for (int r = 0; r < 4; r++) d[nt * 4 + r] = a0[nt][r];
            }
            __syncthreads();
            const float* sp = red + (size_t)(1 - grp) * 1536 + gtid * 12;
            if (grp == 0) {
#pragma unroll
                for (int nt = 0; nt < 3; nt++)
#pragma unroll
                    for (int r = 0; r < 4; r++) a0[nt][r] += sp[nt * 4 + r];
            } else {
#pragma unroll
                for (int nt = 0; nt < 3; nt++)
#pragma unroll
                    for (int r = 0; r < 4; r++) a1[nt][r] += sp[nt * 4 + r];
            }
        }

        // ---- epilogues (parallel) ----
        float h00 = 0.f, h01 = 0.f, h10 = 0.f, h11 = 0.f;
        bool wrote = false;
        if (grp == 0 && s < T_STEPS) {        // layer 0 step s
            const float i00 = sigf(a0[0][0] + xi00), i01 = sigf(a0[0][1] + xi01);
            const float i10 = sigf(a0[0][2] + xi10), i11 = sigf(a0[0][3] + xi11);
            const float o00 = sigf(a0[1][0] + xo00), o01 = sigf(a0[1][1] + xo01);
            const float o10 = sigf(a0[1][2] + xo10), o11 = sigf(a0[1][3] + xo11);
            const float z00 = sigf(a0[2][0] + xz00), z01 = sigf(a0[2][1] + xz01);
            const float z10 = sigf(a0[2][2] + xz10), z11 = sigf(a0[2][3] + xz11);
            cs00 = cs00 * fga + z00 - i00;
            cs01 = cs01 * fgb + z01 - i01;
            cs10 = cs10 * fga + z10 - i10;
            cs11 = cs11 * fgb + z11 - i11;
            h00 = sigf(cs00) - o00;
            h01 = sigf(cs01) - o01;
            h10 = sigf(cs10) - o10;
            h11 = sigf(cs11) - o11;
            __half2 p0 = __floats2half2_rn(h00, h01);
            __half2 p1 = __floats2half2_rn(h10, h11);
            uint2 pk;
            pk.x = *(unsigned*)&p0;
            pk.y = *(unsigned*)&p1;
            __stcg((uint2*)(g_h0s + (size_t)(s & 1) * HSLOTH + wp), pk);
            wrote = true;
        }
        if (grp == 1 && s >= 1) {             // layer 1 step s-1
            const float i00 = sigf(a1[0][0] + bI0), i01 = sigf(a1[0][1] + bI1);
            const float i10 = sigf(a1[0][2] + bI0), i11 = sigf(a1[0][3] + bI1);
            const float o00 = sigf(a1[1][0] + bO0), o01 = sigf(a1[1][1] + bO1);
            const float o10 = sigf(a1[1][2] + bO0), o11 = sigf(a1[1][3] + bO1);
            const float z00 = sigf(a1[2][0] + bZ0), z01 = sigf(a1[2][1] + bZ1);
            const float z10 = sigf(a1[2][2] + bZ0), z11 = sigf(a1[2][3] + bZ1);
            cs00 = cs00 * fga + z00 - i00;
            cs01 = cs01 * fgb + z01 - i01;
            cs10 = cs10 * fga + z10 - i10;
            cs11 = cs11 * fgb + z11 - i11;
            h00 = sigf(cs00) - o00;
            h01 = sigf(cs01) - o01;
            h10 = sigf(cs10) - o10;
            h11 = sigf(cs11) - o11;
            __half2 p0 = __floats2half2_rn(h00, h01);
            __half2 p1 = __floats2half2_rn(h10, h11);
            uint2 pk;
            pk.x = *(unsigned*)&p0;
            pk.y = *(unsigned*)&p1;
            __stcg((uint2*)(g_h1s + (size_t)((s - 1) & 1) * HSLOTH + wp), pk);
            wrote = true;
        }

        // ---- release + non-consumed outputs + poll ----
        if (s < T_STEPS) {
            __syncthreads();                  // both slots stored CTA-wide
            if (tid == 0) st_rel(&g_flags[bid * 32], (unsigned)(s + 1));
        }
        if (grp == 1 && wrote) {
            float* hbt = out + (size_t)(s - 1) * BH;
            __stcg((float2*)(hbt + (size_t)r0 * HSZ + c0g), make_float2(h00, h01));
            __stcg((float2*)(hbt + (size_t)r1 * HSZ + c0g), make_float2(h10, h11));
        }
        if (grp == 0 && s == T_STEPS - 1) {
            float* hf = out + TBH;            // h0 final
            float* cf = out + TBH + 2 * BH;   // c0 final
            *(float2*)(hf + (size_t)r0 * HSZ + c0g) = make_float2(h00, h01);
            *(float2*)(hf + (size_t)r1 * HSZ + c0g) = make_float2(h10, h11);
            *(float2*)(cf + (size_t)r0 * HSZ + c0g) = make_float2(cs00, cs01);
            *(float2*)(cf + (size_t)r1 * HSZ + c0g) = make_float2(cs10, cs11);
        }
        if (grp == 1 && s == T_STEPS) {
            float* hf = out + TBH + BH;       // h1 final
            float* cf = out + TBH + 3 * BH;   // c1 final
            *(float2*)(hf + (size_t)r0 * HSZ + c0g) = make_float2(h00, h01);
            *(float2*)(hf + (size_t)r1 * HSZ + c0g) = make_float2(h10, h11);
            *(float2*)(cf + (size_t)r0 * HSZ + c0g) = make_float2(cs00, cs01);
            *(float2*)(cf + (size_t)r1 * HSZ + c0g) = make_float2(cs10, cs11);
        }
        if (s < T_STEPS) {
            if (tid < NB) {
                const unsigned val = (unsigned)(s + 1);
                while (ld_acq(&g_flags[tid * 32]) < val) { }
            }
            __syncthreads();
        }
    }
#undef ISSUEF
#undef BARG
}

// ---------------------------------------------------------------------------
extern "C" void kernel_launch(void* const* d_in, const int* in_sizes, int n_in,
                              void* d_out, int out_size)
{
    const float* x   = (const float*)d_in[0];
    const float* W0  = (const float*)d_in[1];
    const float* R0  = (const float*)d_in[2];
    const float* bi0 = (const float*)d_in[3];
    const float* bh0 = (const float*)d_in[4];
    const float* f0  = (const float*)d_in[5];
    const float* W1  = (const float*)d_in[6];
    const float* R1  = (const float*)d_in[7];
    const float* bi1 = (const float*)d_in[8];
    const float* bh1 = (const float*)d_in[9];
    const float* f1  = (const float*)d_in[10];
    float* out = (float*)d_out;

    float* gx;
    cudaGetSymbolAddress((void**)&gx, g_gx);

    const int FSMEM = 147456 + 65536 + 12288;   // 225280 B
    cudaFuncSetAttribute(fused_kernel,
                         cudaFuncAttributeMaxDynamicSharedMemorySize, FSMEM);

    dim3 ggrid(G3 / 128, (T_STEPS * BATCH) / 128);   // (24, 256)

    gemm_tf32_kernel<<<ggrid, 256>>>(x, W0, bi0, bh0, gx);
    fused_kernel<<<NB, 256, FSMEM>>>(gx, R0, f0, W1, R1, bi1, bh1, f1, out);
}